// round 15
// baseline (speedup 1.0000x reference)
#include <cuda_runtime.h>
#include <cstdint>
#include <cfloat>

// Problem constants (fixed by the dataset)
constexpr int Bv  = 16;      // batch
constexpr int Nv  = 16384;   // pixels
constexpr int D4v = 16;      // float4 chunks per vector
constexpr int Kv  = 64;      // templates
constexpr int PPB = 2;       // pixels per block (warp-pair each -> all 4 SMSPs)
constexpr int TP  = 17;      // row pitch in float4 (272 B) -> conflict-free banks
constexpr float EPS = 1e-3f; // near-tie margin (>> fp32 dist error ~1e-5)

using ull = unsigned long long;

// ---- packed f32x2 helpers (per-lane rounding identical to fmaf) ----
__device__ __forceinline__ ull f2_fma(ull a, ull b, ull c) {
    ull d;
    asm("fma.rn.f32x2 %0, %1, %2, %3;" : "=l"(d) : "l"(a), "l"(b), "l"(c));
    return d;
}
__device__ __forceinline__ void f2_unpack(ull p, float& lo, float& hi) {
    unsigned a, b;
    asm("mov.b64 {%0, %1}, %2;" : "=r"(a), "=r"(b) : "l"(p));
    lo = __uint_as_float(a); hi = __uint_as_float(b);
}

__device__ __forceinline__ uint32_t smem_u32(const void* p) {
    uint32_t a;
    asm("{ .reg .u64 t; cvta.to.shared.u64 t, %1; cvt.u32.u64 %0, t; }"
        : "=r"(a) : "l"(p));
    return a;
}
__device__ __forceinline__ void bulk_cp(uint32_t dst, const void* src,
                                        uint32_t bytes, uint32_t mbar) {
    asm volatile(
        "cp.async.bulk.shared::cta.global.mbarrier::complete_tx::bytes "
        "[%0], [%1], %2, [%3];"
        :: "r"(dst), "l"(src), "r"(bytes), "r"(mbar) : "memory");
}
__device__ __forceinline__ void mbar_init(uint32_t mbar, uint32_t cnt) {
    asm volatile("mbarrier.init.shared.b64 [%0], %1;" :: "r"(mbar), "r"(cnt) : "memory");
}
__device__ __forceinline__ void mbar_expect_tx(uint32_t mbar, uint32_t bytes) {
    asm volatile("mbarrier.arrive.expect_tx.shared.b64 _, [%0], %1;"
                 :: "r"(mbar), "r"(bytes) : "memory");
}
__device__ __forceinline__ void mbar_wait_parity0(uint32_t mbar) {
    asm volatile(
        "{\n\t"
        ".reg .pred P1;\n\t"
        "WAIT_LOOP_%=:\n\t"
        "mbarrier.try_wait.parity.acquire.cta.shared::cta.b64 P1, [%0], 0, 0x989680;\n\t"
        "@P1 bra.uni WAIT_DONE_%=;\n\t"
        "bra.uni WAIT_LOOP_%=;\n\t"
        "WAIT_DONE_%=:\n\t"
        "}"
        :: "r"(mbar) : "memory");
}

struct Smem {
    float4 ts[PPB][Kv * TP];     // 2 x 17408 B (t tiles, pitch 272 B)
    float4 xs[PPB][Bv * TP];     // 2 x  4352 B (x tiles)
    float  t2s[PPB][Kv];
    float  x2s[PPB][Bv];
    float  clsf[Kv];
    float  rv[PPB][Bv][17];      // pitch 17: conflict-free reduce scan
    int    ri[PPB][Bv][17];
    float  bestvs[PPB][Bv];
    int    bestks[PPB][Bv];
    int    cnt[PPB][Bv];
    ull    refined[PPB][Bv];
    ull    mbar[PPB];
};

__global__ __launch_bounds__(128)
void osc_kernel(const float4* __restrict__ xg,     // frame_embeddings [B,N,D] f32
                const float4* __restrict__ tg,     // templates        [K,N,D] f32
                const int*    __restrict__ tcls,   // template_classes [K] int32
                float* __restrict__ out)
{
    extern __shared__ __align__(16) char smem_raw[];
    Smem& S = *reinterpret_cast<Smem*>(smem_raw);

    const int tid = threadIdx.x;
    const int p   = tid >> 6;            // pixel slot 0/1 (warps 0,1 | 2,3)
    const int q   = tid & 63;            // thread id within pixel
    const int n   = blockIdx.x * PPB + p;

    // ---- init: mbarrier + small tables ----
    if (q == 0) mbar_init(smem_u32(&S.mbar[p]), 1);
    if (tid < Kv) S.clsf[tid] = (float)tcls[tid];
    if (q < Bv) {
        S.cnt[p][q]     = 0;
        S.refined[p][q] = 0xFFFFFFFFFFFFFFFFULL;
    }
    __syncthreads();

    // ---- async bulk staging: 64 t-rows + 16 x-rows of 256 B, pitch 272 B ----
    if (q == 0) {
        const uint32_t mb = smem_u32(&S.mbar[p]);
        mbar_expect_tx(mb, (Kv + Bv) * 256);
        const uint32_t tbase = smem_u32(&S.ts[p][0]);
#pragma unroll 1
        for (int k = 0; k < Kv; ++k)
            bulk_cp(tbase + k * (TP * 16), &tg[((size_t)k * Nv + n) * D4v], 256, mb);
        const uint32_t xbase = smem_u32(&S.xs[p][0]);
#pragma unroll 1
        for (int b = 0; b < Bv; ++b)
            bulk_cp(xbase + b * (TP * 16), &xg[((size_t)b * Nv + n) * D4v], 256, mb);
    }
    mbar_wait_parity0(smem_u32(&S.mbar[p]));   // all threads of this pixel

    // ---- norms: ||t_k||^2 (one row per thread), ||x_b||^2 (q<16) ----
    {
        float s0 = 0.f, s1 = 0.f, s2 = 0.f, s3 = 0.f;
#pragma unroll
        for (int d4 = 0; d4 < D4v; ++d4) {
            float4 v = S.ts[p][q * TP + d4];
            s0 = fmaf(v.x, v.x, s0); s1 = fmaf(v.y, v.y, s1);
            s2 = fmaf(v.z, v.z, s2); s3 = fmaf(v.w, v.w, s3);
        }
        S.t2s[p][q] = (s0 + s1) + (s2 + s3);
    }
    if (q < Bv) {
        float s0 = 0.f, s1 = 0.f, s2 = 0.f, s3 = 0.f;
#pragma unroll
        for (int d4 = 0; d4 < D4v; ++d4) {
            float4 v = S.xs[p][q * TP + d4];
            s0 = fmaf(v.x, v.x, s0); s1 = fmaf(v.y, v.y, s1);
            s2 = fmaf(v.z, v.z, s2); s3 = fmaf(v.w, v.w, s3);
        }
        S.x2s[p][q] = (s0 + s1) + (s2 + s3);
    }
    __syncthreads();

    // ---- Phase A: 4x4 register-tile dot products, packed f32x2 over d ----
    // thread covers b in {c, c+4, c+8, c+12}, k in {r, r+16, r+32, r+48}
    const int c = q & 3;
    const int r = q >> 2;

    ull acc2[4][4];
#pragma unroll
    for (int i = 0; i < 4; ++i)
#pragma unroll
        for (int j = 0; j < 4; ++j) acc2[i][j] = 0ULL;   // (0.f, 0.f)

#pragma unroll 4
    for (int d4 = 0; d4 < D4v; ++d4) {
        ulonglong2 xv[4], tv[4];
#pragma unroll
        for (int i = 0; i < 4; ++i)
            xv[i] = *reinterpret_cast<const ulonglong2*>(&S.xs[p][(c + 4 * i) * TP + d4]);
#pragma unroll
        for (int j = 0; j < 4; ++j)
            tv[j] = *reinterpret_cast<const ulonglong2*>(&S.ts[p][(r + 16 * j) * TP + d4]);
#pragma unroll
        for (int i = 0; i < 4; ++i)
#pragma unroll
            for (int j = 0; j < 4; ++j) {
                acc2[i][j] = f2_fma(xv[i].x, tv[j].x, acc2[i][j]);
                acc2[i][j] = f2_fma(xv[i].y, tv[j].y, acc2[i][j]);
            }
    }

    // distances; per-thread min+argmin over its 4 k's per b
    float df[4][4];
#pragma unroll
    for (int i = 0; i < 4; ++i) {
        const int   b   = c + 4 * i;
        const float bx2 = S.x2s[p][b];
        float bestv = FLT_MAX;
        int   bestk = Kv;
#pragma unroll
        for (int j = 0; j < 4; ++j) {
            const int k = r + 16 * j;
            float lo, hi;
            f2_unpack(acc2[i][j], lo, hi);
            const float d = bx2 + S.t2s[p][k] - 2.0f * (lo + hi);
            df[i][j] = d;
            if (d < bestv) { bestv = d; bestk = k; }  // j asc => first-min
        }
        S.rv[p][b][r] = bestv;
        S.ri[p][b][r] = bestk;
    }
    __syncthreads();

    // ---- fp32 min + argmin per b (q<16) ----
    if (q < Bv) {
        float bestv = S.rv[p][q][0];
        int   bestk = S.ri[p][q][0];
#pragma unroll
        for (int t = 1; t < 16; ++t) {
            const float v = S.rv[p][q][t];
            const int   k = S.ri[p][q][t];
            if (v < bestv || (v == bestv && k < bestk)) { bestv = v; bestk = k; }
        }
        S.bestvs[p][q] = bestv;
        S.bestks[p][q] = bestk;
    }
    __syncthreads();

    // ---- near-tie candidate count per b ----
#pragma unroll
    for (int i = 0; i < 4; ++i) {
        const int b = c + 4 * i;
        const float lim = S.bestvs[p][b] + EPS;
        int local = 0;
#pragma unroll
        for (int j = 0; j < 4; ++j) local += (df[i][j] <= lim) ? 1 : 0;
        if (local) atomicAdd(&S.cnt[p][b], local);
    }
    __syncthreads();

    // ---- Phase B (RARE): exact fp64 refinement for contested b ----
#pragma unroll
    for (int i = 0; i < 4; ++i) {
        const int b = c + 4 * i;
        if (S.cnt[p][b] < 2) continue;                // uncontested: skip fp64
        const float lim = S.bestvs[p][b] + EPS;
#pragma unroll
        for (int j = 0; j < 4; ++j) {
            if (df[i][j] > lim) continue;
            const int k = r + 16 * j;
            double dd = 0.0;
#pragma unroll 1
            for (int d4 = 0; d4 < D4v; ++d4) {
                const float4 xv = S.xs[p][b * TP + d4];
                const float4 tv = S.ts[p][k * TP + d4];
                const double e0 = (double)xv.x - (double)tv.x;
                const double e1 = (double)xv.y - (double)tv.y;
                const double e2 = (double)xv.z - (double)tv.z;
                const double e3 = (double)xv.w - (double)tv.w;
                dd = fma(e0, e0, dd); dd = fma(e1, e1, dd);
                dd = fma(e2, e2, dd); dd = fma(e3, e3, dd);
            }
            const float dfx = (float)dd;              // exact -> fp32
            const ull key = ((ull)__float_as_uint(dfx) << 6) | (ull)k;
            atomicMin(&S.refined[p][b], key);
        }
    }
    __syncthreads();

    // ---- outputs ----
    if (q < Bv) {
        float bestv;
        int   bestk;
        if (S.cnt[p][q] >= 2) {
            const ull key = S.refined[p][q];
            bestk = (int)(key & 63ULL);
            bestv = __uint_as_float((unsigned int)(key >> 6));
        } else {
            bestv = S.bestvs[p][q];
            bestk = S.bestks[p][q];
        }
        const size_t BN = (size_t)Bv * Nv;
        const size_t o  = (size_t)q * Nv + n;
        out[o]           = (bestv <= 0.5f) ? 1.0f : 0.0f;  // mask @ 0.5
        out[BN + o]      = (bestv <= 1.0f) ? 1.0f : 0.0f;  // mask @ 1.0
        out[2 * BN + o]  = bestv;                          // min_dists
        out[3 * BN + o]  = S.clsf[bestk];                  // pred_classes
    }
}

extern "C" void kernel_launch(void* const* d_in, const int* in_sizes, int n_in,
                              void* d_out, int out_size)
{
    const float4* frame = (const float4*)d_in[0];   // [16,16384,64] f32
    const float4* tmpl  = (const float4*)d_in[1];   // [64,16384,64] f32
    const int*    tcls  = (const int*)d_in[2];      // [64] int32
    float*        out   = (float*)d_out;

    const int smem_bytes = (int)sizeof(Smem);
    cudaFuncSetAttribute(osc_kernel,
                         cudaFuncAttributeMaxDynamicSharedMemorySize, smem_bytes);
    osc_kernel<<<Nv / PPB, 64 * PPB, smem_bytes>>>(frame, tmpl, tcls, out);
}

// round 16
// speedup vs baseline: 1.3499x; 1.3499x over previous
#include <cuda_runtime.h>
#include <cstdint>
#include <cfloat>

// Problem constants (fixed by the dataset)
constexpr int Bv  = 16;      // batch
constexpr int Nv  = 16384;   // pixels
constexpr int D4v = 16;      // float4 chunks per vector
constexpr int Kv  = 64;      // templates
constexpr int PPB = 2;       // pixels per block (warp-pair each -> all 4 SMSPs)
constexpr int TP  = 17;      // row pitch in float4 (272 B) -> conflict-free banks
constexpr float EPS = 1e-3f; // near-tie margin (>> fp32 dist error ~1e-5)

using ull = unsigned long long;

// ---- packed f32x2 helpers (per-lane rounding identical to fmaf) ----
__device__ __forceinline__ ull f2_fma(ull a, ull b, ull c) {
    ull d;
    asm("fma.rn.f32x2 %0, %1, %2, %3;" : "=l"(d) : "l"(a), "l"(b), "l"(c));
    return d;
}
__device__ __forceinline__ void f2_unpack(ull p, float& lo, float& hi) {
    unsigned a, b;
    asm("mov.b64 {%0, %1}, %2;" : "=r"(a), "=r"(b) : "l"(p));
    lo = __uint_as_float(a); hi = __uint_as_float(b);
}

__device__ __forceinline__ uint32_t smem_u32(const void* p) {
    uint32_t a;
    asm("{ .reg .u64 t; cvta.to.shared.u64 t, %1; cvt.u32.u64 %0, t; }"
        : "=r"(a) : "l"(p));
    return a;
}
// 16-byte global->shared async copy (LDGSTS), issued by every thread in parallel
__device__ __forceinline__ void cp16(uint32_t dst, const void* src) {
    asm volatile("cp.async.cg.shared.global [%0], [%1], 16;"
                 :: "r"(dst), "l"(src) : "memory");
}
__device__ __forceinline__ void cp_commit_wait_all() {
    asm volatile("cp.async.commit_group;" ::: "memory");
    asm volatile("cp.async.wait_group 0;" ::: "memory");
}

struct Smem {
    float4 ts[PPB][Kv * TP];     // 2 x 17408 B (t tiles, pitch 272 B, affine)
    float4 xs[PPB][Bv * TP];     // 2 x  4352 B (x tiles)
    float  t2s[PPB][Kv];
    float  x2s[PPB][Bv];
    float  clsf[Kv];
    float  rv[PPB][Bv][17];      // pitch 17: conflict-free reduce scan
    int    ri[PPB][Bv][17];
    float  bestvs[PPB][Bv];
    int    bestks[PPB][Bv];
    int    cnt[PPB][Bv];
    ull    refined[PPB][Bv];
};

__global__ __launch_bounds__(128)
void osc_kernel(const float4* __restrict__ xg,     // frame_embeddings [B,N,D] f32
                const float4* __restrict__ tg,     // templates        [K,N,D] f32
                const int*    __restrict__ tcls,   // template_classes [K] int32
                float* __restrict__ out)
{
    extern __shared__ __align__(16) char smem_raw[];
    Smem& S = *reinterpret_cast<Smem*>(smem_raw);

    const int tid = threadIdx.x;
    const int p   = tid >> 6;            // pixel slot 0/1 (warps 0,1 | 2,3)
    const int q   = tid & 63;            // thread id within pixel
    const int n   = blockIdx.x * PPB + p;

    // ---- async staging: each thread copies 16 t-chunks + 4 x-chunks (16B) ----
    {
        const uint32_t tbase = smem_u32(&S.ts[p][0]);
#pragma unroll
        for (int i = 0; i < 16; ++i) {
            int idx = q + i * 64;        // 1024 chunks
            int k   = idx >> 4;
            int d4  = idx & 15;
            cp16(tbase + (k * TP + d4) * 16, &tg[((size_t)k * Nv + n) * D4v + d4]);
        }
        const uint32_t xbase = smem_u32(&S.xs[p][0]);
#pragma unroll
        for (int i = 0; i < 4; ++i) {
            int idx = q + i * 64;        // 256 chunks
            int b   = idx >> 4;
            int d4  = idx & 15;
            cp16(xbase + (b * TP + d4) * 16, &xg[((size_t)b * Nv + n) * D4v + d4]);
        }
        cp_commit_wait_all();
    }
    if (tid < Kv) S.clsf[tid] = (float)tcls[tid];
    if (q < Bv) {
        S.cnt[p][q]     = 0;
        S.refined[p][q] = 0xFFFFFFFFFFFFFFFFULL;
    }
    __syncthreads();

    // ---- norms: ||t_k||^2 (one row per thread), ||x_b||^2 (q<16) ----
    {
        float s0 = 0.f, s1 = 0.f, s2 = 0.f, s3 = 0.f;
#pragma unroll
        for (int d4 = 0; d4 < D4v; ++d4) {
            float4 v = S.ts[p][q * TP + d4];
            s0 = fmaf(v.x, v.x, s0); s1 = fmaf(v.y, v.y, s1);
            s2 = fmaf(v.z, v.z, s2); s3 = fmaf(v.w, v.w, s3);
        }
        S.t2s[p][q] = (s0 + s1) + (s2 + s3);
    }
    if (q < Bv) {
        float s0 = 0.f, s1 = 0.f, s2 = 0.f, s3 = 0.f;
#pragma unroll
        for (int d4 = 0; d4 < D4v; ++d4) {
            float4 v = S.xs[p][q * TP + d4];
            s0 = fmaf(v.x, v.x, s0); s1 = fmaf(v.y, v.y, s1);
            s2 = fmaf(v.z, v.z, s2); s3 = fmaf(v.w, v.w, s3);
        }
        S.x2s[p][q] = (s0 + s1) + (s2 + s3);
    }
    __syncthreads();

    // ---- Phase A: 4x4 register-tile dot products, packed f32x2 over d ----
    // thread covers b in {c, c+4, c+8, c+12}, k in {r, r+16, r+32, r+48}
    // Affine pitch-17 addressing: per-d4 the 8 loads use constant offsets
    // from two incremented base pointers (no XOR recompute).
    const int c = q & 3;
    const int r = q >> 2;

    ull acc2[4][4];
#pragma unroll
    for (int i = 0; i < 4; ++i)
#pragma unroll
        for (int j = 0; j < 4; ++j) acc2[i][j] = 0ULL;   // (0.f, 0.f)

    const char* xrow0 = reinterpret_cast<const char*>(&S.xs[p][c * TP]);
    const char* trow0 = reinterpret_cast<const char*>(&S.ts[p][r * TP]);
    constexpr int XSTEP = 4 * TP * 16;   // b += 4  -> +4352 B (const)
    constexpr int TSTEP = 16 * TP * 16;  // k += 16 -> +17408 B (const)

#pragma unroll 4
    for (int d4 = 0; d4 < D4v; ++d4) {
        ulonglong2 xv[4], tv[4];
#pragma unroll
        for (int i = 0; i < 4; ++i)
            xv[i] = *reinterpret_cast<const ulonglong2*>(xrow0 + i * XSTEP + d4 * 16);
#pragma unroll
        for (int j = 0; j < 4; ++j)
            tv[j] = *reinterpret_cast<const ulonglong2*>(trow0 + j * TSTEP + d4 * 16);
#pragma unroll
        for (int i = 0; i < 4; ++i)
#pragma unroll
            for (int j = 0; j < 4; ++j) {
                acc2[i][j] = f2_fma(xv[i].x, tv[j].x, acc2[i][j]);
                acc2[i][j] = f2_fma(xv[i].y, tv[j].y, acc2[i][j]);
            }
    }

    // distances; per-thread min+argmin over its 4 k's per b
    float df[4][4];
#pragma unroll
    for (int i = 0; i < 4; ++i) {
        const int   b   = c + 4 * i;
        const float bx2 = S.x2s[p][b];
        float bestv = FLT_MAX;
        int   bestk = Kv;
#pragma unroll
        for (int j = 0; j < 4; ++j) {
            const int k = r + 16 * j;
            float lo, hi;
            f2_unpack(acc2[i][j], lo, hi);
            const float d = bx2 + S.t2s[p][k] - 2.0f * (lo + hi);
            df[i][j] = d;
            if (d < bestv) { bestv = d; bestk = k; }  // j asc => first-min
        }
        S.rv[p][b][r] = bestv;
        S.ri[p][b][r] = bestk;
    }
    __syncthreads();

    // ---- fp32 min + argmin per b (q<16) ----
    if (q < Bv) {
        float bestv = S.rv[p][q][0];
        int   bestk = S.ri[p][q][0];
#pragma unroll
        for (int t = 1; t < 16; ++t) {
            const float v = S.rv[p][q][t];
            const int   k = S.ri[p][q][t];
            if (v < bestv || (v == bestv && k < bestk)) { bestv = v; bestk = k; }
        }
        S.bestvs[p][q] = bestv;
        S.bestks[p][q] = bestk;
    }
    __syncthreads();

    // ---- near-tie candidate count per b ----
#pragma unroll
    for (int i = 0; i < 4; ++i) {
        const int b = c + 4 * i;
        const float lim = S.bestvs[p][b] + EPS;
        int local = 0;
#pragma unroll
        for (int j = 0; j < 4; ++j) local += (df[i][j] <= lim) ? 1 : 0;
        if (local) atomicAdd(&S.cnt[p][b], local);
    }
    __syncthreads();

    // ---- Phase B (RARE): exact fp64 refinement for contested b ----
#pragma unroll
    for (int i = 0; i < 4; ++i) {
        const int b = c + 4 * i;
        if (S.cnt[p][b] < 2) continue;                // uncontested: skip fp64
        const float lim = S.bestvs[p][b] + EPS;
#pragma unroll
        for (int j = 0; j < 4; ++j) {
            if (df[i][j] > lim) continue;
            const int k = r + 16 * j;
            double dd = 0.0;
#pragma unroll 1
            for (int d4 = 0; d4 < D4v; ++d4) {
                const float4 xv = S.xs[p][b * TP + d4];
                const float4 tv = S.ts[p][k * TP + d4];
                const double e0 = (double)xv.x - (double)tv.x;
                const double e1 = (double)xv.y - (double)tv.y;
                const double e2 = (double)xv.z - (double)tv.z;
                const double e3 = (double)xv.w - (double)tv.w;
                dd = fma(e0, e0, dd); dd = fma(e1, e1, dd);
                dd = fma(e2, e2, dd); dd = fma(e3, e3, dd);
            }
            const float dfx = (float)dd;              // exact -> fp32
            const ull key = ((ull)__float_as_uint(dfx) << 6) | (ull)k;
            atomicMin(&S.refined[p][b], key);
        }
    }
    __syncthreads();

    // ---- outputs ----
    if (q < Bv) {
        float bestv;
        int   bestk;
        if (S.cnt[p][q] >= 2) {
            const ull key = S.refined[p][q];
            bestk = (int)(key & 63ULL);
            bestv = __uint_as_float((unsigned int)(key >> 6));
        } else {
            bestv = S.bestvs[p][q];
            bestk = S.bestks[p][q];
        }
        const size_t BN = (size_t)Bv * Nv;
        const size_t o  = (size_t)q * Nv + n;
        out[o]           = (bestv <= 0.5f) ? 1.0f : 0.0f;  // mask @ 0.5
        out[BN + o]      = (bestv <= 1.0f) ? 1.0f : 0.0f;  // mask @ 1.0
        out[2 * BN + o]  = bestv;                          // min_dists
        out[3 * BN + o]  = S.clsf[bestk];                  // pred_classes
    }
}

extern "C" void kernel_launch(void* const* d_in, const int* in_sizes, int n_in,
                              void* d_out, int out_size)
{
    const float4* frame = (const float4*)d_in[0];   // [16,16384,64] f32
    const float4* tmpl  = (const float4*)d_in[1];   // [64,16384,64] f32
    const int*    tcls  = (const int*)d_in[2];      // [64] int32
    float*        out   = (float*)d_out;

    const int smem_bytes = (int)sizeof(Smem);
    cudaFuncSetAttribute(osc_kernel,
                         cudaFuncAttributeMaxDynamicSharedMemorySize, smem_bytes);
    osc_kernel<<<Nv / PPB, 64 * PPB, smem_bytes>>>(frame, tmpl, tcls, out);
}